// round 7
// baseline (speedup 1.0000x reference)
#include <cuda_runtime.h>
#include <cuda_bf16.h>
#include <cstdint>
#include <cstddef>

#define BB 8
#define NN 2048
#define DDIM 512

typedef __nv_bfloat16 bf16;

// ---------------------------------------------------------------------------
// Scratch (static device globals: allocation-free rule)
// ---------------------------------------------------------------------------
__device__ bf16 g_xh[(size_t)BB * NN * DDIM];
__device__ bf16 g_xl[(size_t)BB * NN * DDIM];
__device__ bf16 g_wqh[(size_t)DDIM * DDIM];
__device__ bf16 g_wql[(size_t)DDIM * DDIM];
__device__ bf16 g_wkh[(size_t)DDIM * DDIM];
__device__ bf16 g_wkl[(size_t)DDIM * DDIM];
__device__ bf16 g_wvh[(size_t)DDIM * DDIM];
__device__ bf16 g_wvl[(size_t)DDIM * DDIM];
__device__ bf16 g_Qh[(size_t)BB * NN * DDIM];
__device__ bf16 g_Ql[(size_t)BB * NN * DDIM];
__device__ bf16 g_Kh[(size_t)BB * NN * DDIM];
__device__ bf16 g_Kl[(size_t)BB * NN * DDIM];
__device__ bf16 g_Vh[(size_t)BB * NN * DDIM];
__device__ bf16 g_Vl[(size_t)BB * NN * DDIM];
__device__ bf16 g_Wmh[(size_t)BB * NN * NN];
__device__ bf16 g_Wml[(size_t)BB * NN * NN];
__device__ float g_rs[(size_t)BB * NN];

// ---------------------------------------------------------------------------
// Low-level helpers (family-baseline PTX only: cp.async / ldmatrix / mma.sync)
// ---------------------------------------------------------------------------
__device__ __forceinline__ uint32_t smem_to_u32(const void* p) {
    uint32_t a;
    asm("{ .reg .u64 t; cvta.to.shared.u64 t, %1; cvt.u32.u64 %0, t; }"
        : "=r"(a) : "l"(p));
    return a;
}
__device__ __forceinline__ void cp16(uint32_t dst, const void* src) {
    asm volatile("cp.async.cg.shared.global [%0], [%1], 16;" :: "r"(dst), "l"(src));
}
__device__ __forceinline__ void cp_commit() {
    asm volatile("cp.async.commit_group;" ::: "memory");
}
__device__ __forceinline__ void cp_wait1() {
    asm volatile("cp.async.wait_group 1;" ::: "memory");
}
__device__ __forceinline__ void cp_wait0() {
    asm volatile("cp.async.wait_group 0;" ::: "memory");
}
__device__ __forceinline__ void ldsm4(uint32_t* r, uint32_t addr) {
    asm volatile("ldmatrix.sync.aligned.m8n8.x4.shared.b16 {%0,%1,%2,%3}, [%4];"
                 : "=r"(r[0]), "=r"(r[1]), "=r"(r[2]), "=r"(r[3]) : "r"(addr));
}
__device__ __forceinline__ void ldsm4t(uint32_t* r, uint32_t addr) {
    asm volatile("ldmatrix.sync.aligned.m8n8.x4.trans.shared.b16 {%0,%1,%2,%3}, [%4];"
                 : "=r"(r[0]), "=r"(r[1]), "=r"(r[2]), "=r"(r[3]) : "r"(addr));
}
__device__ __forceinline__ void mma16816(float* c, const uint32_t* a, const uint32_t* b) {
    asm volatile(
        "mma.sync.aligned.m16n8k16.row.col.f32.bf16.bf16.f32 "
        "{%0,%1,%2,%3}, {%4,%5,%6,%7}, {%8,%9}, {%0,%1,%2,%3};"
        : "+f"(c[0]), "+f"(c[1]), "+f"(c[2]), "+f"(c[3])
        : "r"(a[0]), "r"(a[1]), "r"(a[2]), "r"(a[3]), "r"(b[0]), "r"(b[1]));
}
__device__ __forceinline__ uint32_t pack_bf16(bf16 a, bf16 b) {
    return (uint32_t)__bfloat16_as_ushort(a) | ((uint32_t)__bfloat16_as_ushort(b) << 16);
}
__device__ __forceinline__ void split_val(float v, bf16& h, bf16& l) {
    h = __float2bfloat16(v);
    l = __float2bfloat16(v - __bfloat162float(h));
}

// ---------------------------------------------------------------------------
// SMEM geometry (K-chunk = 32, padded rows instead of XOR swizzle):
//   k-major slab: 128 rows x 64B data + 16B pad = 80B stride -> 10240 B
//     bank-group(16B) = (5*row + chunk) mod 8 : conflict-free (5 coprime 8)
//   n-major V slab: 32 k-rows x 256B data + 16B pad = 272B stride -> 8704 B
//     bank-group = (17*row + chunk) mod 8 = (row + chunk) mod 8 : conflict-free
// score/qkv stage: Ah|Al|Bh|Bl = 4*10240 = 40960 ; x2 stages = 81920 (2 CTA/SM)
// out stage:       Ah|Al|Vh|Vl = 2*10240+2*8704 = 37888 ; x2 = 75776 (2 CTA/SM)
// ---------------------------------------------------------------------------
static constexpr int SLAB_K = 10240;
static constexpr int SLAB_V = 8704;
static constexpr int STAGE_S = 4 * SLAB_K;              // 40960
static constexpr int STAGE_O = 2 * SLAB_K + 2 * SLAB_V; // 37888
static constexpr int SMEM_S = 2 * STAGE_S;              // 81920
static constexpr int SMEM_O = 2 * STAGE_O;              // 75776

// k-major loader: 128 rows x 32 k (64B/row). 256 threads, 2 cp16 each.
__device__ __forceinline__ void load_km32(const bf16* src, size_t ld, uint32_t sbase, int t)
{
    const int col = t & 3, r0 = t >> 2;   // r0: 0..63
    #pragma unroll
    for (int p = 0; p < 2; p++) {
        const int row = r0 + 64 * p;
        cp16(sbase + row * 80 + col * 16, src + (size_t)row * ld + col * 8);
    }
}
// n-major V loader: 32 k-rows x 128 n (256B/row). 256 threads, 2 cp16 each.
__device__ __forceinline__ void load_bn32(const bf16* src, size_t ld, uint32_t sbase, int t)
{
    const int col = t & 15, r0 = t >> 4;  // r0: 0..15
    #pragma unroll
    for (int p = 0; p < 2; p++) {
        const int row = r0 + 16 * p;
        cp16(sbase + row * 272 + col * 16, src + (size_t)row * ld + col * 8);
    }
}

// 3-product split MMA over one 32-k chunk; warp tile 64(m) x 32(n).
// Warp grid 2(m) x 4(n).  B slab k-major.
__device__ __forceinline__ void compute_nt(uint32_t base, float c[4][4][4],
                                           int lane, int wm0, int wn0)
{
    const uint32_t sAh = base, sAl = base + SLAB_K;
    const uint32_t sBh = base + 2 * SLAB_K, sBl = base + 3 * SLAB_K;
    #pragma unroll
    for (int kk = 0; kk < 2; kk++) {
        uint32_t aH[4][4], aL[4][4];
        const int ar = lane & 15;
        const int ac = 2 * kk + (lane >> 4);
        #pragma unroll
        for (int i = 0; i < 4; i++) {
            const int row = wm0 + i * 16 + ar;
            const uint32_t off = row * 80 + ac * 16;
            ldsm4(aH[i], sAh + off);
            ldsm4(aL[i], sAl + off);
        }
        const int br = (lane & 7) + ((lane >> 4) & 1) * 8;
        const int bc = 2 * kk + ((lane >> 3) & 1);
        #pragma unroll
        for (int jj = 0; jj < 2; jj++) {
            const int row = wn0 + jj * 16 + br;
            const uint32_t off = row * 80 + bc * 16;
            uint32_t tH[4], tL[4];
            ldsm4(tH, sBh + off);
            ldsm4(tL, sBl + off);
            uint32_t b0H[2] = {tH[0], tH[1]}, b1H[2] = {tH[2], tH[3]};
            uint32_t b0L[2] = {tL[0], tL[1]}, b1L[2] = {tL[2], tL[3]};
            #pragma unroll
            for (int i = 0; i < 4; i++) {
                mma16816(c[i][2 * jj], aH[i], b0H);
                mma16816(c[i][2 * jj], aH[i], b0L);
                mma16816(c[i][2 * jj], aL[i], b0H);
                mma16816(c[i][2 * jj + 1], aH[i], b1H);
                mma16816(c[i][2 * jj + 1], aH[i], b1L);
                mma16816(c[i][2 * jj + 1], aL[i], b1H);
            }
        }
    }
}

// Same, B slab n-major via ldmatrix.trans.
__device__ __forceinline__ void compute_tr(uint32_t base, float c[4][4][4],
                                           int lane, int wm0, int wn0)
{
    const uint32_t sAh = base, sAl = base + SLAB_K;
    const uint32_t sVh = base + 2 * SLAB_K, sVl = base + 2 * SLAB_K + SLAB_V;
    #pragma unroll
    for (int kk = 0; kk < 2; kk++) {
        uint32_t aH[4][4], aL[4][4];
        const int ar = lane & 15;
        const int ac = 2 * kk + (lane >> 4);
        #pragma unroll
        for (int i = 0; i < 4; i++) {
            const int row = wm0 + i * 16 + ar;
            const uint32_t off = row * 80 + ac * 16;
            ldsm4(aH[i], sAh + off);
            ldsm4(aL[i], sAl + off);
        }
        const int br = kk * 16 + (lane & 7) + ((lane >> 3) & 1) * 8;
        #pragma unroll
        for (int jj = 0; jj < 2; jj++) {
            const int ch = (wn0 >> 3) + 2 * jj + (lane >> 4);
            const uint32_t off = br * 272 + ch * 16;
            uint32_t tH[4], tL[4];
            ldsm4t(tH, sVh + off);
            ldsm4t(tL, sVl + off);
            uint32_t b0H[2] = {tH[0], tH[1]}, b1H[2] = {tH[2], tH[3]};
            uint32_t b0L[2] = {tL[0], tL[1]}, b1L[2] = {tL[2], tL[3]};
            #pragma unroll
            for (int i = 0; i < 4; i++) {
                mma16816(c[i][2 * jj], aH[i], b0H);
                mma16816(c[i][2 * jj], aH[i], b0L);
                mma16816(c[i][2 * jj], aL[i], b0H);
                mma16816(c[i][2 * jj + 1], aH[i], b1H);
                mma16816(c[i][2 * jj + 1], aH[i], b1L);
                mma16816(c[i][2 * jj + 1], aL[i], b1H);
            }
        }
    }
}

#define ZERO_ACC(c)                                  \
    _Pragma("unroll")                                \
    for (int i = 0; i < 4; i++)                      \
        _Pragma("unroll")                            \
        for (int j = 0; j < 4; j++)                  \
            _Pragma("unroll")                        \
            for (int k = 0; k < 4; k++) c[i][j][k] = 0.f;

// ---------------------------------------------------------------------------
// Kernel 1: QKV projections. CTA tile 128(m) x 128(n), 256 threads, 2 CTA/SM.
// ---------------------------------------------------------------------------
__global__ __launch_bounds__(256, 2)
void qkv_mma_kernel(const float* __restrict__ bq, const float* __restrict__ bk,
                    const float* __restrict__ bv)
{
    extern __shared__ char smem[];
    const uint32_t sb = smem_to_u32(smem);
    const int tid = threadIdx.x, wid = tid >> 5, lane = tid & 31;
    const int wm0 = (wid & 1) * 64, wn0 = (wid >> 1) * 32;

    const int n0 = blockIdx.x * 128, m0 = blockIdx.y * 128, z = blockIdx.z;
    const bf16 *Wh_, *Wl_;
    const float* bias;
    bf16 *Dh, *Dl;
    if (z == 0)      { Wh_ = g_wqh; Wl_ = g_wql; bias = bq; Dh = g_Qh; Dl = g_Ql; }
    else if (z == 1) { Wh_ = g_wkh; Wl_ = g_wkl; bias = bk; Dh = g_Kh; Dl = g_Kl; }
    else             { Wh_ = g_wvh; Wl_ = g_wvl; bias = bv; Dh = g_Vh; Dl = g_Vl; }

    const bf16* Ah = g_xh + (size_t)m0 * DDIM;
    const bf16* Al = g_xl + (size_t)m0 * DDIM;
    const bf16* Bh = Wh_ + (size_t)n0 * DDIM;
    const bf16* Bl = Wl_ + (size_t)n0 * DDIM;

    const int NIT = DDIM / 32;
    load_km32(Ah, DDIM, sb, tid);
    load_km32(Al, DDIM, sb + SLAB_K, tid);
    load_km32(Bh, DDIM, sb + 2 * SLAB_K, tid);
    load_km32(Bl, DDIM, sb + 3 * SLAB_K, tid);
    cp_commit();

    float c[4][4][4];
    ZERO_ACC(c);

    for (int it = 0; it < NIT; it++) {
        if (it + 1 < NIT) {
            const uint32_t d = sb + ((it + 1) & 1) * STAGE_S;
            const size_t ko = (size_t)(it + 1) * 32;
            load_km32(Ah + ko, DDIM, d, tid);
            load_km32(Al + ko, DDIM, d + SLAB_K, tid);
            load_km32(Bh + ko, DDIM, d + 2 * SLAB_K, tid);
            load_km32(Bl + ko, DDIM, d + 3 * SLAB_K, tid);
            cp_commit();
            cp_wait1();
        } else cp_wait0();
        __syncthreads();
        compute_nt(sb + (it & 1) * STAGE_S, c, lane, wm0, wn0);
        __syncthreads();
    }

    #pragma unroll
    for (int i = 0; i < 4; i++)
        #pragma unroll
        for (int h = 0; h < 2; h++) {
            const int m = m0 + wm0 + i * 16 + (lane >> 2) + 8 * h;
            #pragma unroll
            for (int j = 0; j < 4; j++) {
                const int col = n0 + wn0 + j * 8 + 2 * (lane & 3);
                const float2 bs = *(const float2*)(bias + col);
                const float v0 = c[i][j][2 * h] + bs.x;
                const float v1 = c[i][j][2 * h + 1] + bs.y;
                bf16 h0, h1, l0, l1;
                split_val(v0, h0, l0);
                split_val(v1, h1, l1);
                const size_t idx = (size_t)m * DDIM + col;
                *(uint32_t*)(Dh + idx) = pack_bf16(h0, h1);
                *(uint32_t*)(Dl + idx) = pack_bf16(l0, l1);
            }
        }
}

// ---------------------------------------------------------------------------
// Kernel 2: scores + mask*exp + split store W + fused rowsum atomics.
// CTA tile 128(q) x 128(c), 256 threads, 2 CTA/SM.
// ---------------------------------------------------------------------------
__global__ __launch_bounds__(256, 2)
void score_mma_kernel(const float* __restrict__ adj)
{
    extern __shared__ char smem[];
    const uint32_t sb = smem_to_u32(smem);
    const int tid = threadIdx.x, wid = tid >> 5, lane = tid & 31;
    const int wm0 = (wid & 1) * 64, wn0 = (wid >> 1) * 32;

    const int c0 = blockIdx.x * 128, q0 = blockIdx.y * 128, b = blockIdx.z;

    const bf16* Ah = g_Qh + ((size_t)b * NN + q0) * DDIM;
    const bf16* Al = g_Ql + ((size_t)b * NN + q0) * DDIM;
    const bf16* Bh = g_Kh + ((size_t)b * NN + c0) * DDIM;
    const bf16* Bl = g_Kl + ((size_t)b * NN + c0) * DDIM;

    const int NIT = DDIM / 32;
    load_km32(Ah, DDIM, sb, tid);
    load_km32(Al, DDIM, sb + SLAB_K, tid);
    load_km32(Bh, DDIM, sb + 2 * SLAB_K, tid);
    load_km32(Bl, DDIM, sb + 3 * SLAB_K, tid);
    cp_commit();

    float c[4][4][4];
    ZERO_ACC(c);

    for (int it = 0; it < NIT; it++) {
        if (it + 1 < NIT) {
            const uint32_t d = sb + ((it + 1) & 1) * STAGE_S;
            const size_t ko = (size_t)(it + 1) * 32;
            load_km32(Ah + ko, DDIM, d, tid);
            load_km32(Al + ko, DDIM, d + SLAB_K, tid);
            load_km32(Bh + ko, DDIM, d + 2 * SLAB_K, tid);
            load_km32(Bl + ko, DDIM, d + 3 * SLAB_K, tid);
            cp_commit();
            cp_wait1();
        } else cp_wait0();
        __syncthreads();
        compute_nt(sb + (it & 1) * STAGE_S, c, lane, wm0, wn0);
        __syncthreads();
    }

    #pragma unroll
    for (int i = 0; i < 4; i++)
        #pragma unroll
        for (int h = 0; h < 2; h++) {
            const int r = q0 + wm0 + i * 16 + (lane >> 2) + 8 * h;
            const size_t rowbase = ((size_t)b * NN + r) * NN;
            float rsum = 0.f;
            #pragma unroll
            for (int j = 0; j < 4; j++) {
                const int cc = c0 + wn0 + j * 8 + 2 * (lane & 3);
                const float2 a2 = *(const float2*)(adj + rowbase + cc);
                const float w0 = a2.x * __expf(c[i][j][2 * h]);
                const float w1 = a2.y * __expf(c[i][j][2 * h + 1]);
                rsum += w0 + w1;
                bf16 h0, h1, l0, l1;
                split_val(w0, h0, l0);
                split_val(w1, h1, l1);
                *(uint32_t*)(g_Wmh + rowbase + cc) = pack_bf16(h0, h1);
                *(uint32_t*)(g_Wml + rowbase + cc) = pack_bf16(l0, l1);
            }
            rsum += __shfl_xor_sync(0xffffffffu, rsum, 1);
            rsum += __shfl_xor_sync(0xffffffffu, rsum, 2);
            if ((lane & 3) == 0)
                atomicAdd(&g_rs[b * NN + r], rsum);
        }
}

// ---------------------------------------------------------------------------
// Kernel 3: O = (W @ V) / rowsum.  CTA tile 128(q) x 128(n), 2 CTA/SM.
// ---------------------------------------------------------------------------
__global__ __launch_bounds__(256, 2)
void out_mma_kernel(float* __restrict__ out)
{
    extern __shared__ char smem[];
    const uint32_t sb = smem_to_u32(smem);
    const int tid = threadIdx.x, wid = tid >> 5, lane = tid & 31;
    const int wm0 = (wid & 1) * 64, wn0 = (wid >> 1) * 32;

    const int n0 = blockIdx.x * 128, q0 = blockIdx.y * 128, b = blockIdx.z;

    const bf16* Ah = g_Wmh + ((size_t)b * NN + q0) * NN;
    const bf16* Al = g_Wml + ((size_t)b * NN + q0) * NN;
    const bf16* Bh = g_Vh + (size_t)b * NN * DDIM + n0;
    const bf16* Bl = g_Vl + (size_t)b * NN * DDIM + n0;

    const int NIT = NN / 32;
    load_km32(Ah, NN, sb, tid);
    load_km32(Al, NN, sb + SLAB_K, tid);
    load_bn32(Bh, DDIM, sb + 2 * SLAB_K, tid);
    load_bn32(Bl, DDIM, sb + 2 * SLAB_K + SLAB_V, tid);
    cp_commit();

    float c[4][4][4];
    ZERO_ACC(c);

    for (int it = 0; it < NIT; it++) {
        if (it + 1 < NIT) {
            const uint32_t d = sb + ((it + 1) & 1) * STAGE_O;
            const size_t ko = (size_t)(it + 1) * 32;
            load_km32(Ah + ko, NN, d, tid);
            load_km32(Al + ko, NN, d + SLAB_K, tid);
            load_bn32(Bh + ko * DDIM, DDIM, d + 2 * SLAB_K, tid);
            load_bn32(Bl + ko * DDIM, DDIM, d + 2 * SLAB_K + SLAB_V, tid);
            cp_commit();
            cp_wait1();
        } else cp_wait0();
        __syncthreads();
        compute_tr(sb + (it & 1) * STAGE_O, c, lane, wm0, wn0);
        __syncthreads();
    }

    #pragma unroll
    for (int i = 0; i < 4; i++)
        #pragma unroll
        for (int h = 0; h < 2; h++) {
            const int r = q0 + wm0 + i * 16 + (lane >> 2) + 8 * h;
            const float inv = 1.0f / g_rs[b * NN + r];
            float* op = out + ((size_t)b * NN + r) * DDIM;
            #pragma unroll
            for (int j = 0; j < 4; j++) {
                const int col = n0 + wn0 + j * 8 + 2 * (lane & 3);
                float2 v;
                v.x = c[i][j][2 * h] * inv;
                v.y = c[i][j][2 * h + 1] * inv;
                *(float2*)(op + col) = v;
            }
        }
}

// ---------------------------------------------------------------------------
// Elementwise: fp32 -> (hi, lo) bf16 split;  rowsum zero
// ---------------------------------------------------------------------------
__global__ void split_kernel(const float* __restrict__ src,
                             bf16* __restrict__ h, bf16* __restrict__ l, int n4)
{
    int i = blockIdx.x * blockDim.x + threadIdx.x;
    if (i >= n4) return;
    float4 v = ((const float4*)src)[i];
    bf16 h0, h1, h2, h3, l0, l1, l2, l3;
    split_val(v.x, h0, l0); split_val(v.y, h1, l1);
    split_val(v.z, h2, l2); split_val(v.w, h3, l3);
    ((uint2*)h)[i] = make_uint2(pack_bf16(h0, h1), pack_bf16(h2, h3));
    ((uint2*)l)[i] = make_uint2(pack_bf16(l0, l1), pack_bf16(l2, l3));
}

__global__ void zero_rs_kernel() {
    g_rs[blockIdx.x * 256 + threadIdx.x] = 0.f;
}

// ---------------------------------------------------------------------------
extern "C" void kernel_launch(void* const* d_in, const int* in_sizes, int n_in,
                              void* d_out, int out_size)
{
    const float* x    = (const float*)d_in[0];
    const float* adj  = (const float*)d_in[1];
    const float* Wq_w = (const float*)d_in[2];
    const float* Wq_b = (const float*)d_in[3];
    const float* Wk_w = (const float*)d_in[4];
    const float* Wk_b = (const float*)d_in[5];
    const float* Wv_w = (const float*)d_in[6];
    const float* Wv_b = (const float*)d_in[7];
    float* out = (float*)d_out;

    cudaFuncSetAttribute(qkv_mma_kernel, cudaFuncAttributeMaxDynamicSharedMemorySize, SMEM_S);
    cudaFuncSetAttribute(score_mma_kernel, cudaFuncAttributeMaxDynamicSharedMemorySize, SMEM_S);
    cudaFuncSetAttribute(out_mma_kernel, cudaFuncAttributeMaxDynamicSharedMemorySize, SMEM_O);

    bf16 *xh, *xl, *wqh, *wql, *wkh, *wkl, *wvh, *wvl;
    cudaGetSymbolAddress((void**)&xh, g_xh);   cudaGetSymbolAddress((void**)&xl, g_xl);
    cudaGetSymbolAddress((void**)&wqh, g_wqh); cudaGetSymbolAddress((void**)&wql, g_wql);
    cudaGetSymbolAddress((void**)&wkh, g_wkh); cudaGetSymbolAddress((void**)&wkl, g_wkl);
    cudaGetSymbolAddress((void**)&wvh, g_wvh); cudaGetSymbolAddress((void**)&wvl, g_wvl);

    {
        int n4 = BB * NN * DDIM / 4;
        split_kernel<<<(n4 + 255) / 256, 256>>>(x, xh, xl, n4);
        int w4 = DDIM * DDIM / 4;
        split_kernel<<<(w4 + 255) / 256, 256>>>(Wq_w, wqh, wql, w4);
        split_kernel<<<(w4 + 255) / 256, 256>>>(Wk_w, wkh, wkl, w4);
        split_kernel<<<(w4 + 255) / 256, 256>>>(Wv_w, wvh, wvl, w4);
    }
    zero_rs_kernel<<<(BB * NN) / 256, 256>>>();

    {
        dim3 grid(DDIM / 128, BB * NN / 128, 3);
        qkv_mma_kernel<<<grid, 256, SMEM_S>>>(Wq_b, Wk_b, Wv_b);
    }
    {
        dim3 grid(NN / 128, NN / 128, BB);
        score_mma_kernel<<<grid, 256, SMEM_S>>>(adj);
    }
    {
        dim3 grid(DDIM / 128, NN / 128, BB);
        out_mma_kernel<<<grid, 256, SMEM_O>>>(out);
    }
}

// round 8
// speedup vs baseline: 1.1721x; 1.1721x over previous
#include <cuda_runtime.h>
#include <cuda_bf16.h>
#include <cstdint>
#include <cstddef>

#define BB 8
#define NN 2048
#define DDIM 512

typedef __nv_bfloat16 bf16;

// ---------------------------------------------------------------------------
// Scratch (static device globals: allocation-free rule)
// ---------------------------------------------------------------------------
__device__ bf16 g_xh[(size_t)BB * NN * DDIM];
__device__ bf16 g_xl[(size_t)BB * NN * DDIM];
__device__ bf16 g_wqh[(size_t)DDIM * DDIM];
__device__ bf16 g_wql[(size_t)DDIM * DDIM];
__device__ bf16 g_wkh[(size_t)DDIM * DDIM];
__device__ bf16 g_wkl[(size_t)DDIM * DDIM];
__device__ bf16 g_wvh[(size_t)DDIM * DDIM];
__device__ bf16 g_wvl[(size_t)DDIM * DDIM];
__device__ bf16 g_Qh[(size_t)BB * NN * DDIM];
__device__ bf16 g_Ql[(size_t)BB * NN * DDIM];
__device__ bf16 g_Kh[(size_t)BB * NN * DDIM];
__device__ bf16 g_Kl[(size_t)BB * NN * DDIM];
__device__ bf16 g_Vh[(size_t)BB * NN * DDIM];
__device__ bf16 g_Vl[(size_t)BB * NN * DDIM];
__device__ bf16 g_Wmh[(size_t)BB * NN * NN];
__device__ bf16 g_Wml[(size_t)BB * NN * NN];
__device__ float g_rs[(size_t)BB * NN];

// ---------------------------------------------------------------------------
// Low-level helpers (family-baseline PTX only: cp.async / ldmatrix / mma.sync)
// ---------------------------------------------------------------------------
__device__ __forceinline__ uint32_t smem_to_u32(const void* p) {
    uint32_t a;
    asm("{ .reg .u64 t; cvta.to.shared.u64 t, %1; cvt.u32.u64 %0, t; }"
        : "=r"(a) : "l"(p));
    return a;
}
__device__ __forceinline__ void cp16(uint32_t dst, const void* src) {
    asm volatile("cp.async.cg.shared.global [%0], [%1], 16;" :: "r"(dst), "l"(src));
}
__device__ __forceinline__ void cp_commit() {
    asm volatile("cp.async.commit_group;" ::: "memory");
}
__device__ __forceinline__ void cp_wait1() {
    asm volatile("cp.async.wait_group 1;" ::: "memory");
}
__device__ __forceinline__ void cp_wait0() {
    asm volatile("cp.async.wait_group 0;" ::: "memory");
}
__device__ __forceinline__ void ldsm4(uint32_t* r, uint32_t addr) {
    asm volatile("ldmatrix.sync.aligned.m8n8.x4.shared.b16 {%0,%1,%2,%3}, [%4];"
                 : "=r"(r[0]), "=r"(r[1]), "=r"(r[2]), "=r"(r[3]) : "r"(addr));
}
__device__ __forceinline__ void ldsm4t(uint32_t* r, uint32_t addr) {
    asm volatile("ldmatrix.sync.aligned.m8n8.x4.trans.shared.b16 {%0,%1,%2,%3}, [%4];"
                 : "=r"(r[0]), "=r"(r[1]), "=r"(r[2]), "=r"(r[3]) : "r"(addr));
}
__device__ __forceinline__ void mma16816(float* c, const uint32_t* a, const uint32_t* b) {
    asm volatile(
        "mma.sync.aligned.m16n8k16.row.col.f32.bf16.bf16.f32 "
        "{%0,%1,%2,%3}, {%4,%5,%6,%7}, {%8,%9}, {%0,%1,%2,%3};"
        : "+f"(c[0]), "+f"(c[1]), "+f"(c[2]), "+f"(c[3])
        : "r"(a[0]), "r"(a[1]), "r"(a[2]), "r"(a[3]), "r"(b[0]), "r"(b[1]));
}
__device__ __forceinline__ uint32_t pack_bf16(bf16 a, bf16 b) {
    return (uint32_t)__bfloat16_as_ushort(a) | ((uint32_t)__bfloat16_as_ushort(b) << 16);
}
__device__ __forceinline__ void split_val(float v, bf16& h, bf16& l) {
    h = __float2bfloat16(v);
    l = __float2bfloat16(v - __bfloat162float(h));
}

// ---------------------------------------------------------------------------
// SMEM: 3 stages x (Ah 16K | Al 16K | Bh 16K | Bl 16K) = 192 KB
// k-major slab: 128 rows x 128B (64 bf16), XOR-swizzled 16B chunks.
// n-major V slab (out kernel): 64 k-rows x 256B (128 bf16).
// ---------------------------------------------------------------------------
static constexpr int SLAB = 16384;
static constexpr int STAGE = 4 * SLAB;        // 65536
static constexpr int SMEM_TOTAL = 3 * STAGE;  // 196608

// k-major loader: 128 rows x 64 k. 256 threads, 4 cp16 each.
__device__ __forceinline__ void load_km(const bf16* src, size_t ld, uint32_t sbase, int t)
{
    const int col = t & 7, r0 = t >> 3;   // r0: 0..31
    #pragma unroll
    for (int p = 0; p < 4; p++) {
        const int row = r0 + 32 * p;
        const uint32_t off = row * 128 + ((col ^ (row & 7)) << 4);
        cp16(sbase + off, src + (size_t)row * ld + col * 8);
    }
}
// n-major V loader: 64 k-rows x 128 n-cols. 256 threads, 4 cp16 each.
__device__ __forceinline__ void load_bn(const bf16* src, size_t ld, uint32_t sbase, int t)
{
    const int col = t & 15, r0 = t >> 4;  // r0: 0..15
    #pragma unroll
    for (int p = 0; p < 4; p++) {
        const int row = r0 + 16 * p;
        const uint32_t off = row * 256 + ((col ^ (row & 7)) << 4);
        cp16(sbase + off, src + (size_t)row * ld + col * 8);
    }
}

// 3-product split MMA over one 64-k chunk; warp tile 64(m) x 32(n).
// Warp grid 2(m) x 4(n).  B slab k-major.
__device__ __forceinline__ void compute_nt(uint32_t base, float c[4][4][4],
                                           int lane, int wm0, int wn0)
{
    const uint32_t sAh = base, sAl = base + SLAB;
    const uint32_t sBh = base + 2 * SLAB, sBl = base + 3 * SLAB;
    #pragma unroll
    for (int kk = 0; kk < 4; kk++) {
        uint32_t aH[4][4], aL[4][4];
        const int ar = lane & 15;
        const int ac = 2 * kk + (lane >> 4);
        #pragma unroll
        for (int i = 0; i < 4; i++) {
            const int row = wm0 + i * 16 + ar;
            const uint32_t off = row * 128 + ((ac ^ (row & 7)) << 4);
            ldsm4(aH[i], sAh + off);
            ldsm4(aL[i], sAl + off);
        }
        const int br = (lane & 7) + ((lane >> 4) & 1) * 8;
        const int bc = 2 * kk + ((lane >> 3) & 1);
        #pragma unroll
        for (int jj = 0; jj < 2; jj++) {
            const int row = wn0 + jj * 16 + br;
            const uint32_t off = row * 128 + ((bc ^ (row & 7)) << 4);
            uint32_t tH[4], tL[4];
            ldsm4(tH, sBh + off);
            ldsm4(tL, sBl + off);
            uint32_t b0H[2] = {tH[0], tH[1]}, b1H[2] = {tH[2], tH[3]};
            uint32_t b0L[2] = {tL[0], tL[1]}, b1L[2] = {tL[2], tL[3]};
            #pragma unroll
            for (int i = 0; i < 4; i++) {
                mma16816(c[i][2 * jj], aH[i], b0H);
                mma16816(c[i][2 * jj], aH[i], b0L);
                mma16816(c[i][2 * jj], aL[i], b0H);
                mma16816(c[i][2 * jj + 1], aH[i], b1H);
                mma16816(c[i][2 * jj + 1], aH[i], b1L);
                mma16816(c[i][2 * jj + 1], aL[i], b1H);
            }
        }
    }
}

// Same, B slab n-major via ldmatrix.trans.
__device__ __forceinline__ void compute_tr(uint32_t base, float c[4][4][4],
                                           int lane, int wm0, int wn0)
{
    const uint32_t sAh = base, sAl = base + SLAB;
    const uint32_t sVh = base + 2 * SLAB, sVl = base + 3 * SLAB;
    #pragma unroll
    for (int kk = 0; kk < 4; kk++) {
        uint32_t aH[4][4], aL[4][4];
        const int ar = lane & 15;
        const int ac = 2 * kk + (lane >> 4);
        #pragma unroll
        for (int i = 0; i < 4; i++) {
            const int row = wm0 + i * 16 + ar;
            const uint32_t off = row * 128 + ((ac ^ (row & 7)) << 4);
            ldsm4(aH[i], sAh + off);
            ldsm4(aL[i], sAl + off);
        }
        const int br = kk * 16 + (lane & 7) + ((lane >> 3) & 1) * 8;
        #pragma unroll
        for (int jj = 0; jj < 2; jj++) {
            const int ch = (wn0 >> 3) + 2 * jj + (lane >> 4);
            const uint32_t off = br * 256 + ((ch ^ (br & 7)) << 4);
            uint32_t tH[4], tL[4];
            ldsm4t(tH, sVh + off);
            ldsm4t(tL, sVl + off);
            uint32_t b0H[2] = {tH[0], tH[1]}, b1H[2] = {tH[2], tH[3]};
            uint32_t b0L[2] = {tL[0], tL[1]}, b1L[2] = {tL[2], tL[3]};
            #pragma unroll
            for (int i = 0; i < 4; i++) {
                mma16816(c[i][2 * jj], aH[i], b0H);
                mma16816(c[i][2 * jj], aH[i], b0L);
                mma16816(c[i][2 * jj], aL[i], b0H);
                mma16816(c[i][2 * jj + 1], aH[i], b1H);
                mma16816(c[i][2 * jj + 1], aH[i], b1L);
                mma16816(c[i][2 * jj + 1], aL[i], b1H);
            }
        }
    }
}

#define ZERO_ACC(c)                                  \
    _Pragma("unroll")                                \
    for (int i = 0; i < 4; i++)                      \
        _Pragma("unroll")                            \
        for (int j = 0; j < 4; j++)                  \
            _Pragma("unroll")                        \
            for (int k = 0; k < 4; k++) c[i][j][k] = 0.f;

// ---------------------------------------------------------------------------
// Kernel 1: QKV projections. CTA tile 128(m) x 128(n), 256 threads.
// 3-stage pipeline, one __syncthreads per chunk.
// ---------------------------------------------------------------------------
__global__ __launch_bounds__(256, 1)
void qkv_mma_kernel(const float* __restrict__ bq, const float* __restrict__ bk,
                    const float* __restrict__ bv)
{
    extern __shared__ char smem[];
    const uint32_t sb = smem_to_u32(smem);
    const int tid = threadIdx.x, wid = tid >> 5, lane = tid & 31;
    const int wm0 = (wid & 1) * 64, wn0 = (wid >> 1) * 32;

    const int n0 = blockIdx.x * 128, m0 = blockIdx.y * 128, z = blockIdx.z;
    const bf16 *Wh_, *Wl_;
    const float* bias;
    bf16 *Dh, *Dl;
    if (z == 0)      { Wh_ = g_wqh; Wl_ = g_wql; bias = bq; Dh = g_Qh; Dl = g_Ql; }
    else if (z == 1) { Wh_ = g_wkh; Wl_ = g_wkl; bias = bk; Dh = g_Kh; Dl = g_Kl; }
    else             { Wh_ = g_wvh; Wl_ = g_wvl; bias = bv; Dh = g_Vh; Dl = g_Vl; }

    const bf16* Ah = g_xh + (size_t)m0 * DDIM;
    const bf16* Al = g_xl + (size_t)m0 * DDIM;
    const bf16* Bh = Wh_ + (size_t)n0 * DDIM;
    const bf16* Bl = Wl_ + (size_t)n0 * DDIM;

    const int NIT = DDIM / 64;
    #pragma unroll
    for (int s = 0; s < 2; s++) {
        const uint32_t d = sb + s * STAGE;
        const size_t ko = (size_t)s * 64;
        load_km(Ah + ko, DDIM, d, tid);
        load_km(Al + ko, DDIM, d + SLAB, tid);
        load_km(Bh + ko, DDIM, d + 2 * SLAB, tid);
        load_km(Bl + ko, DDIM, d + 3 * SLAB, tid);
        cp_commit();
    }

    float c[4][4][4];
    ZERO_ACC(c);

    for (int it = 0; it < NIT; it++) {
        if (it < NIT - 1) cp_wait1(); else cp_wait0();
        __syncthreads();
        compute_nt(sb + (it % 3) * STAGE, c, lane, wm0, wn0);
        if (it + 2 < NIT) {
            const uint32_t d = sb + ((it + 2) % 3) * STAGE;
            const size_t ko = (size_t)(it + 2) * 64;
            load_km(Ah + ko, DDIM, d, tid);
            load_km(Al + ko, DDIM, d + SLAB, tid);
            load_km(Bh + ko, DDIM, d + 2 * SLAB, tid);
            load_km(Bl + ko, DDIM, d + 3 * SLAB, tid);
            cp_commit();
        }
    }

    #pragma unroll
    for (int i = 0; i < 4; i++)
        #pragma unroll
        for (int h = 0; h < 2; h++) {
            const int m = m0 + wm0 + i * 16 + (lane >> 2) + 8 * h;
            #pragma unroll
            for (int j = 0; j < 4; j++) {
                const int col = n0 + wn0 + j * 8 + 2 * (lane & 3);
                const float2 bs = *(const float2*)(bias + col);
                const float v0 = c[i][j][2 * h] + bs.x;
                const float v1 = c[i][j][2 * h + 1] + bs.y;
                bf16 h0, h1, l0, l1;
                split_val(v0, h0, l0);
                split_val(v1, h1, l1);
                const size_t idx = (size_t)m * DDIM + col;
                *(uint32_t*)(Dh + idx) = pack_bf16(h0, h1);
                *(uint32_t*)(Dl + idx) = pack_bf16(l0, l1);
            }
        }
}

// ---------------------------------------------------------------------------
// Kernel 2: scores + mask*exp + split store W + fused rowsum atomics.
// CTA tile 128(q) x 128(c), 256 threads, 3-stage/1-sync.
// ---------------------------------------------------------------------------
__global__ __launch_bounds__(256, 1)
void score_mma_kernel(const float* __restrict__ adj)
{
    extern __shared__ char smem[];
    const uint32_t sb = smem_to_u32(smem);
    const int tid = threadIdx.x, wid = tid >> 5, lane = tid & 31;
    const int wm0 = (wid & 1) * 64, wn0 = (wid >> 1) * 32;

    const int c0 = blockIdx.x * 128, q0 = blockIdx.y * 128, b = blockIdx.z;

    const bf16* Ah = g_Qh + ((size_t)b * NN + q0) * DDIM;
    const bf16* Al = g_Ql + ((size_t)b * NN + q0) * DDIM;
    const bf16* Bh = g_Kh + ((size_t)b * NN + c0) * DDIM;
    const bf16* Bl = g_Kl + ((size_t)b * NN + c0) * DDIM;

    const int NIT = DDIM / 64;
    #pragma unroll
    for (int s = 0; s < 2; s++) {
        const uint32_t d = sb + s * STAGE;
        const size_t ko = (size_t)s * 64;
        load_km(Ah + ko, DDIM, d, tid);
        load_km(Al + ko, DDIM, d + SLAB, tid);
        load_km(Bh + ko, DDIM, d + 2 * SLAB, tid);
        load_km(Bl + ko, DDIM, d + 3 * SLAB, tid);
        cp_commit();
    }

    float c[4][4][4];
    ZERO_ACC(c);

    for (int it = 0; it < NIT; it++) {
        if (it < NIT - 1) cp_wait1(); else cp_wait0();
        __syncthreads();
        compute_nt(sb + (it % 3) * STAGE, c, lane, wm0, wn0);
        if (it + 2 < NIT) {
            const uint32_t d = sb + ((it + 2) % 3) * STAGE;
            const size_t ko = (size_t)(it + 2) * 64;
            load_km(Ah + ko, DDIM, d, tid);
            load_km(Al + ko, DDIM, d + SLAB, tid);
            load_km(Bh + ko, DDIM, d + 2 * SLAB, tid);
            load_km(Bl + ko, DDIM, d + 3 * SLAB, tid);
            cp_commit();
        }
    }

    #pragma unroll
    for (int i = 0; i < 4; i++)
        #pragma unroll
        for (int h = 0; h < 2; h++) {
            const int r = q0 + wm0 + i * 16 + (lane >> 2) + 8 * h;
            const size_t rowbase = ((size_t)b * NN + r) * NN;
            float rsum = 0.f;
            #pragma unroll
            for (int j = 0; j < 4; j++) {
                const int cc = c0 + wn0 + j * 8 + 2 * (lane & 3);
                const float2 a2 = *(const float2*)(adj + rowbase + cc);
                const float w0 = a2.x * __expf(c[i][j][2 * h]);
                const float w1 = a2.y * __expf(c[i][j][2 * h + 1]);
                rsum += w0 + w1;
                bf16 h0, h1, l0, l1;
                split_val(w0, h0, l0);
                split_val(w1, h1, l1);
                *(uint32_t*)(g_Wmh + rowbase + cc) = pack_bf16(h0, h1);
                *(uint32_t*)(g_Wml + rowbase + cc) = pack_bf16(l0, l1);
            }
            rsum += __shfl_xor_sync(0xffffffffu, rsum, 1);
            rsum += __shfl_xor_sync(0xffffffffu, rsum, 2);
            if ((lane & 3) == 0)
                atomicAdd(&g_rs[b * NN + r], rsum);
        }
}

// ---------------------------------------------------------------------------
// Kernel 3: O = (W @ V) / rowsum.  CTA tile 128(q) x 128(n), 3-stage/1-sync.
// ---------------------------------------------------------------------------
__global__ __launch_bounds__(256, 1)
void out_mma_kernel(float* __restrict__ out)
{
    extern __shared__ char smem[];
    const uint32_t sb = smem_to_u32(smem);
    const int tid = threadIdx.x, wid = tid >> 5, lane = tid & 31;
    const int wm0 = (wid & 1) * 64, wn0 = (wid >> 1) * 32;

    const int n0 = blockIdx.x * 128, q0 = blockIdx.y * 128, b = blockIdx.z;

    const bf16* Ah = g_Wmh + ((size_t)b * NN + q0) * NN;
    const bf16* Al = g_Wml + ((size_t)b * NN + q0) * NN;
    const bf16* Bh = g_Vh + (size_t)b * NN * DDIM + n0;
    const bf16* Bl = g_Vl + (size_t)b * NN * DDIM + n0;

    const int NIT = NN / 64;
    #pragma unroll
    for (int s = 0; s < 2; s++) {
        const uint32_t d = sb + s * STAGE;
        const size_t ko = (size_t)s * 64;
        load_km(Ah + ko, NN, d, tid);
        load_km(Al + ko, NN, d + SLAB, tid);
        load_bn(Bh + ko * DDIM, DDIM, d + 2 * SLAB, tid);
        load_bn(Bl + ko * DDIM, DDIM, d + 3 * SLAB, tid);
        cp_commit();
    }

    float c[4][4][4];
    ZERO_ACC(c);

    for (int it = 0; it < NIT; it++) {
        if (it < NIT - 1) cp_wait1(); else cp_wait0();
        __syncthreads();
        compute_tr(sb + (it % 3) * STAGE, c, lane, wm0, wn0);
        if (it + 2 < NIT) {
            const uint32_t d = sb + ((it + 2) % 3) * STAGE;
            const size_t ko = (size_t)(it + 2) * 64;
            load_km(Ah + ko, NN, d, tid);
            load_km(Al + ko, NN, d + SLAB, tid);
            load_bn(Bh + ko * DDIM, DDIM, d + 2 * SLAB, tid);
            load_bn(Bl + ko * DDIM, DDIM, d + 3 * SLAB, tid);
            cp_commit();
        }
    }

    #pragma unroll
    for (int i = 0; i < 4; i++)
        #pragma unroll
        for (int h = 0; h < 2; h++) {
            const int r = q0 + wm0 + i * 16 + (lane >> 2) + 8 * h;
            const float inv = 1.0f / g_rs[b * NN + r];
            float* op = out + ((size_t)b * NN + r) * DDIM;
            #pragma unroll
            for (int j = 0; j < 4; j++) {
                const int col = n0 + wn0 + j * 8 + 2 * (lane & 3);
                float2 v;
                v.x = c[i][j][2 * h] * inv;
                v.y = c[i][j][2 * h + 1] * inv;
                *(float2*)(op + col) = v;
            }
        }
}

// ---------------------------------------------------------------------------
// Prep: all fp32 -> (hi, lo) bf16 splits + rowsum zero, ONE launch.
// ---------------------------------------------------------------------------
static constexpr int NX4 = BB * NN * DDIM / 4;   // 2097152 quads in x
static constexpr int NW4 = DDIM * DDIM / 4;      // 65536 quads per weight
static constexpr int NPREP = NX4 + 3 * NW4;      // 2293760

__global__ void prep_kernel(const float* __restrict__ x,
                            const float* __restrict__ wq,
                            const float* __restrict__ wk,
                            const float* __restrict__ wv)
{
    const int i = blockIdx.x * blockDim.x + threadIdx.x;
    if (i < BB * NN) g_rs[i] = 0.f;
    if (i >= NPREP) return;

    const float* src;
    bf16 *h, *l;
    int j;
    if (i < NX4)               { src = x;  h = g_xh;  l = g_xl;  j = i; }
    else if (i < NX4 + NW4)    { src = wq; h = g_wqh; l = g_wql; j = i - NX4; }
    else if (i < NX4 + 2*NW4)  { src = wk; h = g_wkh; l = g_wkl; j = i - NX4 - NW4; }
    else                       { src = wv; h = g_wvh; l = g_wvl; j = i - NX4 - 2*NW4; }

    float4 v = ((const float4*)src)[j];
    bf16 h0, h1, h2, h3, l0, l1, l2, l3;
    split_val(v.x, h0, l0); split_val(v.y, h1, l1);
    split_val(v.z, h2, l2); split_val(v.w, h3, l3);
    ((uint2*)h)[j] = make_uint2(pack_bf16(h0, h1), pack_bf16(h2, h3));
    ((uint2*)l)[j] = make_uint2(pack_bf16(l0, l1), pack_bf16(l2, l3));
}

// ---------------------------------------------------------------------------
extern "C" void kernel_launch(void* const* d_in, const int* in_sizes, int n_in,
                              void* d_out, int out_size)
{
    const float* x    = (const float*)d_in[0];
    const float* adj  = (const float*)d_in[1];
    const float* Wq_w = (const float*)d_in[2];
    const float* Wq_b = (const float*)d_in[3];
    const float* Wk_w = (const float*)d_in[4];
    const float* Wk_b = (const float*)d_in[5];
    const float* Wv_w = (const float*)d_in[6];
    const float* Wv_b = (const float*)d_in[7];
    float* out = (float*)d_out;

    cudaFuncSetAttribute(qkv_mma_kernel, cudaFuncAttributeMaxDynamicSharedMemorySize, SMEM_TOTAL);
    cudaFuncSetAttribute(score_mma_kernel, cudaFuncAttributeMaxDynamicSharedMemorySize, SMEM_TOTAL);
    cudaFuncSetAttribute(out_mma_kernel, cudaFuncAttributeMaxDynamicSharedMemorySize, SMEM_TOTAL);

    prep_kernel<<<(NPREP + 255) / 256, 256>>>(x, Wq_w, Wk_w, Wv_w);

    {
        dim3 grid(DDIM / 128, BB * NN / 128, 3);
        qkv_mma_kernel<<<grid, 256, SMEM_TOTAL>>>(Wq_b, Wk_b, Wv_b);
    }
    {
        dim3 grid(NN / 128, NN / 128, BB);
        score_mma_kernel<<<grid, 256, SMEM_TOTAL>>>(adj);
    }
    {
        dim3 grid(DDIM / 128, NN / 128, BB);
        out_mma_kernel<<<grid, 256, SMEM_TOTAL>>>(out);
    }
}

// round 9
// speedup vs baseline: 1.1738x; 1.0015x over previous
#include <cuda_runtime.h>
#include <cuda_bf16.h>
#include <cstdint>
#include <cstddef>

#define BB 8
#define NN 2048
#define DDIM 512

typedef __nv_bfloat16 bf16;

// ---------------------------------------------------------------------------
// Scratch (static device globals: allocation-free rule)
// ---------------------------------------------------------------------------
__device__ bf16 g_xh[(size_t)BB * NN * DDIM];
__device__ bf16 g_xl[(size_t)BB * NN * DDIM];
__device__ bf16 g_wqh[(size_t)DDIM * DDIM];
__device__ bf16 g_wql[(size_t)DDIM * DDIM];
__device__ bf16 g_wkh[(size_t)DDIM * DDIM];
__device__ bf16 g_wkl[(size_t)DDIM * DDIM];
__device__ bf16 g_wvh[(size_t)DDIM * DDIM];
__device__ bf16 g_wvl[(size_t)DDIM * DDIM];
__device__ bf16 g_Qh[(size_t)BB * NN * DDIM];
__device__ bf16 g_Ql[(size_t)BB * NN * DDIM];
__device__ bf16 g_Kh[(size_t)BB * NN * DDIM];
__device__ bf16 g_Kl[(size_t)BB * NN * DDIM];
__device__ bf16 g_Vh[(size_t)BB * NN * DDIM];
__device__ bf16 g_Vl[(size_t)BB * NN * DDIM];
__device__ bf16 g_Wmh[(size_t)BB * NN * NN];
__device__ bf16 g_Wml[(size_t)BB * NN * NN];
__device__ float g_rs[(size_t)BB * NN];

// ---------------------------------------------------------------------------
// Low-level helpers (family-baseline PTX only: cp.async / ldmatrix / mma.sync)
// ---------------------------------------------------------------------------
__device__ __forceinline__ uint32_t smem_to_u32(const void* p) {
    uint32_t a;
    asm("{ .reg .u64 t; cvta.to.shared.u64 t, %1; cvt.u32.u64 %0, t; }"
        : "=r"(a) : "l"(p));
    return a;
}
__device__ __forceinline__ void cp16(uint32_t dst, const void* src) {
    asm volatile("cp.async.cg.shared.global [%0], [%1], 16;" :: "r"(dst), "l"(src));
}
__device__ __forceinline__ void cp_commit() {
    asm volatile("cp.async.commit_group;" ::: "memory");
}
__device__ __forceinline__ void cp_wait1() {
    asm volatile("cp.async.wait_group 1;" ::: "memory");
}
__device__ __forceinline__ void cp_wait0() {
    asm volatile("cp.async.wait_group 0;" ::: "memory");
}
__device__ __forceinline__ void ldsm4(uint32_t* r, uint32_t addr) {
    asm volatile("ldmatrix.sync.aligned.m8n8.x4.shared.b16 {%0,%1,%2,%3}, [%4];"
                 : "=r"(r[0]), "=r"(r[1]), "=r"(r[2]), "=r"(r[3]) : "r"(addr));
}
__device__ __forceinline__ void ldsm4t(uint32_t* r, uint32_t addr) {
    asm volatile("ldmatrix.sync.aligned.m8n8.x4.trans.shared.b16 {%0,%1,%2,%3}, [%4];"
                 : "=r"(r[0]), "=r"(r[1]), "=r"(r[2]), "=r"(r[3]) : "r"(addr));
}
__device__ __forceinline__ void mma16816(float* c, const uint32_t* a, const uint32_t* b) {
    asm volatile(
        "mma.sync.aligned.m16n8k16.row.col.f32.bf16.bf16.f32 "
        "{%0,%1,%2,%3}, {%4,%5,%6,%7}, {%8,%9}, {%0,%1,%2,%3};"
        : "+f"(c[0]), "+f"(c[1]), "+f"(c[2]), "+f"(c[3])
        : "r"(a[0]), "r"(a[1]), "r"(a[2]), "r"(a[3]), "r"(b[0]), "r"(b[1]));
}
__device__ __forceinline__ uint32_t pack_bf16(bf16 a, bf16 b) {
    return (uint32_t)__bfloat16_as_ushort(a) | ((uint32_t)__bfloat16_as_ushort(b) << 16);
}
__device__ __forceinline__ void split_val(float v, bf16& h, bf16& l) {
    h = __float2bfloat16(v);
    l = __float2bfloat16(v - __bfloat162float(h));
}

// ---------------------------------------------------------------------------
// SMEM: 3 stages x (Ah 16K | Al 16K | Bh 16K | Bl 16K) = 192 KB
// k-major slab: 128 rows x 128B (64 bf16), XOR-swizzled 16B chunks.
// n-major V slab (out kernel): 64 k-rows x 256B (128 bf16).
// ---------------------------------------------------------------------------
static constexpr int SLAB = 16384;
static constexpr int STAGE = 4 * SLAB;        // 65536
static constexpr int SMEM_TOTAL = 3 * STAGE;  // 196608

// k-major loader: 128 rows x 64 k. 256 threads, 4 cp16 each.
__device__ __forceinline__ void load_km(const bf16* src, size_t ld, uint32_t sbase, int t)
{
    const int col = t & 7, r0 = t >> 3;   // r0: 0..31
    #pragma unroll
    for (int p = 0; p < 4; p++) {
        const int row = r0 + 32 * p;
        const uint32_t off = row * 128 + ((col ^ (row & 7)) << 4);
        cp16(sbase + off, src + (size_t)row * ld + col * 8);
    }
}
// n-major V loader: 64 k-rows x 128 n-cols. 256 threads, 4 cp16 each.
__device__ __forceinline__ void load_bn(const bf16* src, size_t ld, uint32_t sbase, int t)
{
    const int col = t & 15, r0 = t >> 4;  // r0: 0..15
    #pragma unroll
    for (int p = 0; p < 4; p++) {
        const int row = r0 + 16 * p;
        const uint32_t off = row * 256 + ((col ^ (row & 7)) << 4);
        cp16(sbase + off, src + (size_t)row * ld + col * 8);
    }
}

// ---------------------------------------------------------------------------
// Fragment loaders (one kk step = 16 k-values)
// ---------------------------------------------------------------------------
__device__ __forceinline__ void lda_frag(uint32_t sAh, uint32_t sAl, int kk, int lane,
                                         int wm0, uint32_t aH[4][4], uint32_t aL[4][4])
{
    const int ar = lane & 15;
    const int ac = 2 * kk + (lane >> 4);
    #pragma unroll
    for (int i = 0; i < 4; i++) {
        const int row = wm0 + i * 16 + ar;
        const uint32_t off = row * 128 + ((ac ^ (row & 7)) << 4);
        ldsm4(aH[i], sAh + off);
        ldsm4(aL[i], sAl + off);
    }
}
__device__ __forceinline__ void ldb_frag_nt(uint32_t sBh, uint32_t sBl, int kk, int lane,
                                            int wn0, uint32_t bH[4][2], uint32_t bL[4][2])
{
    const int br = (lane & 7) + ((lane >> 4) & 1) * 8;
    const int bc = 2 * kk + ((lane >> 3) & 1);
    #pragma unroll
    for (int jj = 0; jj < 2; jj++) {
        const int row = wn0 + jj * 16 + br;
        const uint32_t off = row * 128 + ((bc ^ (row & 7)) << 4);
        uint32_t tH[4], tL[4];
        ldsm4(tH, sBh + off);
        ldsm4(tL, sBl + off);
        bH[2 * jj][0] = tH[0]; bH[2 * jj][1] = tH[1];
        bH[2 * jj + 1][0] = tH[2]; bH[2 * jj + 1][1] = tH[3];
        bL[2 * jj][0] = tL[0]; bL[2 * jj][1] = tL[1];
        bL[2 * jj + 1][0] = tL[2]; bL[2 * jj + 1][1] = tL[3];
    }
}
__device__ __forceinline__ void ldb_frag_tr(uint32_t sVh, uint32_t sVl, int kk, int lane,
                                            int wn0, uint32_t bH[4][2], uint32_t bL[4][2])
{
    const int br = kk * 16 + (lane & 7) + ((lane >> 3) & 1) * 8;
    #pragma unroll
    for (int jj = 0; jj < 2; jj++) {
        const int ch = (wn0 >> 3) + 2 * jj + (lane >> 4);
        const uint32_t off = br * 256 + ((ch ^ (br & 7)) << 4);
        uint32_t tH[4], tL[4];
        ldsm4t(tH, sVh + off);
        ldsm4t(tL, sVl + off);
        bH[2 * jj][0] = tH[0]; bH[2 * jj][1] = tH[1];
        bH[2 * jj + 1][0] = tH[2]; bH[2 * jj + 1][1] = tH[3];
        bL[2 * jj][0] = tL[0]; bL[2 * jj][1] = tL[1];
        bL[2 * jj + 1][0] = tL[2]; bL[2 * jj + 1][1] = tL[3];
    }
}

// 48 MMAs of one kk step (3-product split scheme).
__device__ __forceinline__ void mma_block(float c[4][4][4],
                                          uint32_t aH[4][4], uint32_t aL[4][4],
                                          uint32_t bH[4][2], uint32_t bL[4][2])
{
    #pragma unroll
    for (int j = 0; j < 4; j++)
        #pragma unroll
        for (int i = 0; i < 4; i++) {
            mma16816(c[i][j], aH[i], bH[j]);
            mma16816(c[i][j], aH[i], bL[j]);
            mma16816(c[i][j], aL[i], bH[j]);
        }
}

// Software-pipelined compute over one 64-k chunk: fragment regs double-buffered;
// kk+1's 12 ldmatrix issue before kk's 48 MMAs so LDS latency hides under HMMA.
__device__ __forceinline__ void compute_nt(uint32_t base, float c[4][4][4],
                                           int lane, int wm0, int wn0)
{
    const uint32_t sAh = base, sAl = base + SLAB;
    const uint32_t sBh = base + 2 * SLAB, sBl = base + 3 * SLAB;
    uint32_t aH[2][4][4], aL[2][4][4], bH[2][4][2], bL[2][4][2];
    lda_frag(sAh, sAl, 0, lane, wm0, aH[0], aL[0]);
    ldb_frag_nt(sBh, sBl, 0, lane, wn0, bH[0], bL[0]);
    #pragma unroll
    for (int kk = 0; kk < 4; kk++) {
        const int cur = kk & 1;
        if (kk < 3) {
            lda_frag(sAh, sAl, kk + 1, lane, wm0, aH[cur ^ 1], aL[cur ^ 1]);
            ldb_frag_nt(sBh, sBl, kk + 1, lane, wn0, bH[cur ^ 1], bL[cur ^ 1]);
        }
        mma_block(c, aH[cur], aL[cur], bH[cur], bL[cur]);
    }
}

__device__ __forceinline__ void compute_tr(uint32_t base, float c[4][4][4],
                                           int lane, int wm0, int wn0)
{
    const uint32_t sAh = base, sAl = base + SLAB;
    const uint32_t sVh = base + 2 * SLAB, sVl = base + 3 * SLAB;
    uint32_t aH[2][4][4], aL[2][4][4], bH[2][4][2], bL[2][4][2];
    lda_frag(sAh, sAl, 0, lane, wm0, aH[0], aL[0]);
    ldb_frag_tr(sVh, sVl, 0, lane, wn0, bH[0], bL[0]);
    #pragma unroll
    for (int kk = 0; kk < 4; kk++) {
        const int cur = kk & 1;
        if (kk < 3) {
            lda_frag(sAh, sAl, kk + 1, lane, wm0, aH[cur ^ 1], aL[cur ^ 1]);
            ldb_frag_tr(sVh, sVl, kk + 1, lane, wn0, bH[cur ^ 1], bL[cur ^ 1]);
        }
        mma_block(c, aH[cur], aL[cur], bH[cur], bL[cur]);
    }
}

#define ZERO_ACC(c)                                  \
    _Pragma("unroll")                                \
    for (int i = 0; i < 4; i++)                      \
        _Pragma("unroll")                            \
        for (int j = 0; j < 4; j++)                  \
            _Pragma("unroll")                        \
            for (int k = 0; k < 4; k++) c[i][j][k] = 0.f;

// ---------------------------------------------------------------------------
// Kernel 1: QKV projections. CTA tile 128(m) x 128(n), 256 threads.
// 3-stage pipeline, one __syncthreads per chunk.
// ---------------------------------------------------------------------------
__global__ __launch_bounds__(256, 1)
void qkv_mma_kernel(const float* __restrict__ bq, const float* __restrict__ bk,
                    const float* __restrict__ bv)
{
    extern __shared__ char smem[];
    const uint32_t sb = smem_to_u32(smem);
    const int tid = threadIdx.x, wid = tid >> 5, lane = tid & 31;
    const int wm0 = (wid & 1) * 64, wn0 = (wid >> 1) * 32;

    const int n0 = blockIdx.x * 128, m0 = blockIdx.y * 128, z = blockIdx.z;
    const bf16 *Wh_, *Wl_;
    const float* bias;
    bf16 *Dh, *Dl;
    if (z == 0)      { Wh_ = g_wqh; Wl_ = g_wql; bias = bq; Dh = g_Qh; Dl = g_Ql; }
    else if (z == 1) { Wh_ = g_wkh; Wl_ = g_wkl; bias = bk; Dh = g_Kh; Dl = g_Kl; }
    else             { Wh_ = g_wvh; Wl_ = g_wvl; bias = bv; Dh = g_Vh; Dl = g_Vl; }

    const bf16* Ah = g_xh + (size_t)m0 * DDIM;
    const bf16* Al = g_xl + (size_t)m0 * DDIM;
    const bf16* Bh = Wh_ + (size_t)n0 * DDIM;
    const bf16* Bl = Wl_ + (size_t)n0 * DDIM;

    const int NIT = DDIM / 64;
    #pragma unroll
    for (int s = 0; s < 2; s++) {
        const uint32_t d = sb + s * STAGE;
        const size_t ko = (size_t)s * 64;
        load_km(Ah + ko, DDIM, d, tid);
        load_km(Al + ko, DDIM, d + SLAB, tid);
        load_km(Bh + ko, DDIM, d + 2 * SLAB, tid);
        load_km(Bl + ko, DDIM, d + 3 * SLAB, tid);
        cp_commit();
    }

    float c[4][4][4];
    ZERO_ACC(c);

    for (int it = 0; it < NIT; it++) {
        if (it < NIT - 1) cp_wait1(); else cp_wait0();
        __syncthreads();
        compute_nt(sb + (it % 3) * STAGE, c, lane, wm0, wn0);
        if (it + 2 < NIT) {
            const uint32_t d = sb + ((it + 2) % 3) * STAGE;
            const size_t ko = (size_t)(it + 2) * 64;
            load_km(Ah + ko, DDIM, d, tid);
            load_km(Al + ko, DDIM, d + SLAB, tid);
            load_km(Bh + ko, DDIM, d + 2 * SLAB, tid);
            load_km(Bl + ko, DDIM, d + 3 * SLAB, tid);
            cp_commit();
        }
    }

    #pragma unroll
    for (int i = 0; i < 4; i++)
        #pragma unroll
        for (int h = 0; h < 2; h++) {
            const int m = m0 + wm0 + i * 16 + (lane >> 2) + 8 * h;
            #pragma unroll
            for (int j = 0; j < 4; j++) {
                const int col = n0 + wn0 + j * 8 + 2 * (lane & 3);
                const float2 bs = *(const float2*)(bias + col);
                const float v0 = c[i][j][2 * h] + bs.x;
                const float v1 = c[i][j][2 * h + 1] + bs.y;
                bf16 h0, h1, l0, l1;
                split_val(v0, h0, l0);
                split_val(v1, h1, l1);
                const size_t idx = (size_t)m * DDIM + col;
                *(uint32_t*)(Dh + idx) = pack_bf16(h0, h1);
                *(uint32_t*)(Dl + idx) = pack_bf16(l0, l1);
            }
        }
}

// ---------------------------------------------------------------------------
// Kernel 2: scores + mask*exp + split store W + fused rowsum atomics.
// CTA tile 128(q) x 128(c), 256 threads, 3-stage/1-sync.
// ---------------------------------------------------------------------------
__global__ __launch_bounds__(256, 1)
void score_mma_kernel(const float* __restrict__ adj)
{
    extern __shared__ char smem[];
    const uint32_t sb = smem_to_u32(smem);
    const int tid = threadIdx.x, wid = tid >> 5, lane = tid & 31;
    const int wm0 = (wid & 1) * 64, wn0 = (wid >> 1) * 32;

    const int c0 = blockIdx.x * 128, q0 = blockIdx.y * 128, b = blockIdx.z;

    const bf16* Ah = g_Qh + ((size_t)b * NN + q0) * DDIM;
    const bf16* Al = g_Ql + ((size_t)b * NN + q0) * DDIM;
    const bf16* Bh = g_Kh + ((size_t)b * NN + c0) * DDIM;
    const bf16* Bl = g_Kl + ((size_t)b * NN + c0) * DDIM;

    const int NIT = DDIM / 64;
    #pragma unroll
    for (int s = 0; s < 2; s++) {
        const uint32_t d = sb + s * STAGE;
        const size_t ko = (size_t)s * 64;
        load_km(Ah + ko, DDIM, d, tid);
        load_km(Al + ko, DDIM, d + SLAB, tid);
        load_km(Bh + ko, DDIM, d + 2 * SLAB, tid);
        load_km(Bl + ko, DDIM, d + 3 * SLAB, tid);
        cp_commit();
    }

    float c[4][4][4];
    ZERO_ACC(c);

    for (int it = 0; it < NIT; it++) {
        if (it < NIT - 1) cp_wait1(); else cp_wait0();
        __syncthreads();
        compute_nt(sb + (it % 3) * STAGE, c, lane, wm0, wn0);
        if (it + 2 < NIT) {
            const uint32_t d = sb + ((it + 2) % 3) * STAGE;
            const size_t ko = (size_t)(it + 2) * 64;
            load_km(Ah + ko, DDIM, d, tid);
            load_km(Al + ko, DDIM, d + SLAB, tid);
            load_km(Bh + ko, DDIM, d + 2 * SLAB, tid);
            load_km(Bl + ko, DDIM, d + 3 * SLAB, tid);
            cp_commit();
        }
    }

    #pragma unroll
    for (int i = 0; i < 4; i++)
        #pragma unroll
        for (int h = 0; h < 2; h++) {
            const int r = q0 + wm0 + i * 16 + (lane >> 2) + 8 * h;
            const size_t rowbase = ((size_t)b * NN + r) * NN;
            float rsum = 0.f;
            #pragma unroll
            for (int j = 0; j < 4; j++) {
                const int cc = c0 + wn0 + j * 8 + 2 * (lane & 3);
                const float2 a2 = *(const float2*)(adj + rowbase + cc);
                const float w0 = a2.x * __expf(c[i][j][2 * h]);
                const float w1 = a2.y * __expf(c[i][j][2 * h + 1]);
                rsum += w0 + w1;
                bf16 h0, h1, l0, l1;
                split_val(w0, h0, l0);
                split_val(w1, h1, l1);
                *(uint32_t*)(g_Wmh + rowbase + cc) = pack_bf16(h0, h1);
                *(uint32_t*)(g_Wml + rowbase + cc) = pack_bf16(l0, l1);
            }
            rsum += __shfl_xor_sync(0xffffffffu, rsum, 1);
            rsum += __shfl_xor_sync(0xffffffffu, rsum, 2);
            if ((lane & 3) == 0)
                atomicAdd(&g_rs[b * NN + r], rsum);
        }
}

// ---------------------------------------------------------------------------
// Kernel 3: O = (W @ V) / rowsum.  CTA tile 128(q) x 128(n), 3-stage/1-sync.
// ---------------------------------------------------------------------------
__global__ __launch_bounds__(256, 1)
void out_mma_kernel(float* __restrict__ out)
{
    extern __shared__ char smem[];
    const uint32_t sb = smem_to_u32(smem);
    const int tid = threadIdx.x, wid = tid >> 5, lane = tid & 31;
    const int wm0 = (wid & 1) * 64, wn0 = (wid >> 1) * 32;

    const int n0 = blockIdx.x * 128, q0 = blockIdx.y * 128, b = blockIdx.z;

    const bf16* Ah = g_Wmh + ((size_t)b * NN + q0) * NN;
    const bf16* Al = g_Wml + ((size_t)b * NN + q0) * NN;
    const bf16* Bh = g_Vh + (size_t)b * NN * DDIM + n0;
    const bf16* Bl = g_Vl + (size_t)b * NN * DDIM + n0;

    const int NIT = NN / 64;
    #pragma unroll
    for (int s = 0; s < 2; s++) {
        const uint32_t d = sb + s * STAGE;
        const size_t ko = (size_t)s * 64;
        load_km(Ah + ko, NN, d, tid);
        load_km(Al + ko, NN, d + SLAB, tid);
        load_bn(Bh + ko * DDIM, DDIM, d + 2 * SLAB, tid);
        load_bn(Bl + ko * DDIM, DDIM, d + 3 * SLAB, tid);
        cp_commit();
    }

    float c[4][4][4];
    ZERO_ACC(c);

    for (int it = 0; it < NIT; it++) {
        if (it < NIT - 1) cp_wait1(); else cp_wait0();
        __syncthreads();
        compute_tr(sb + (it % 3) * STAGE, c, lane, wm0, wn0);
        if (it + 2 < NIT) {
            const uint32_t d = sb + ((it + 2) % 3) * STAGE;
            const size_t ko = (size_t)(it + 2) * 64;
            load_km(Ah + ko, NN, d, tid);
            load_km(Al + ko, NN, d + SLAB, tid);
            load_bn(Bh + ko * DDIM, DDIM, d + 2 * SLAB, tid);
            load_bn(Bl + ko * DDIM, DDIM, d + 3 * SLAB, tid);
            cp_commit();
        }
    }

    #pragma unroll
    for (int i = 0; i < 4; i++)
        #pragma unroll
        for (int h = 0; h < 2; h++) {
            const int r = q0 + wm0 + i * 16 + (lane >> 2) + 8 * h;
            const float inv = 1.0f / g_rs[b * NN + r];
            float* op = out + ((size_t)b * NN + r) * DDIM;
            #pragma unroll
            for (int j = 0; j < 4; j++) {
                const int col = n0 + wn0 + j * 8 + 2 * (lane & 3);
                float2 v;
                v.x = c[i][j][2 * h] * inv;
                v.y = c[i][j][2 * h + 1] * inv;
                *(float2*)(op + col) = v;
            }
        }
}

// ---------------------------------------------------------------------------
// Prep: all fp32 -> (hi, lo) bf16 splits + rowsum zero, ONE launch.
// ---------------------------------------------------------------------------
static constexpr int NX4 = BB * NN * DDIM / 4;
static constexpr int NW4 = DDIM * DDIM / 4;
static constexpr int NPREP = NX4 + 3 * NW4;

__global__ void prep_kernel(const float* __restrict__ x,
                            const float* __restrict__ wq,
                            const float* __restrict__ wk,
                            const float* __restrict__ wv)
{
    const int i = blockIdx.x * blockDim.x + threadIdx.x;
    if (i < BB * NN) g_rs[i] = 0.f;
    if (i >= NPREP) return;

    const float* src;
    bf16 *h, *l;
    int j;
    if (i < NX4)               { src = x;  h = g_xh;  l = g_xl;  j = i; }
    else if (i < NX4 + NW4)    { src = wq; h = g_wqh; l = g_wql; j = i - NX4; }
    else if (i < NX4 + 2*NW4)  { src = wk; h = g_wkh; l = g_wkl; j = i - NX4 - NW4; }
    else                       { src = wv; h = g_wvh; l = g_wvl; j = i - NX4 - 2*NW4; }

    float4 v = ((const float4*)src)[j];
    bf16 h0, h1, h2, h3, l0, l1, l2, l3;
    split_val(v.x, h0, l0); split_val(v.y, h1, l1);
    split_val(v.z, h2, l2); split_val(v.w, h3, l3);
    ((uint2*)h)[j] = make_uint2(pack_bf16(h0, h1), pack_bf16(h2, h3));
    ((uint2*)l)[j] = make_uint2(pack_bf16(l0, l1), pack_bf16(l2, l3));
}

// ---------------------------------------------------------------------------
extern "C" void kernel_launch(void* const* d_in, const int* in_sizes, int n_in,
                              void* d_out, int out_size)
{
    const float* x    = (const float*)d_in[0];
    const float* adj  = (const float*)d_in[1];
    const float* Wq_w = (const float*)d_in[2];
    const float* Wq_b = (const float*)d_in[3];
    const float* Wk_w = (const float*)d_in[4];
    const float* Wk_b = (const float*)d_in[5];
    const float* Wv_w = (const float*)d_in[6];
    const float* Wv_b = (const float*)d_in[7];
    float* out = (float*)d_out;

    cudaFuncSetAttribute(qkv_mma_kernel, cudaFuncAttributeMaxDynamicSharedMemorySize, SMEM_TOTAL);
    cudaFuncSetAttribute(score_mma_kernel, cudaFuncAttributeMaxDynamicSharedMemorySize, SMEM_TOTAL);
    cudaFuncSetAttribute(out_mma_kernel, cudaFuncAttributeMaxDynamicSharedMemorySize, SMEM_TOTAL);

    prep_kernel<<<(NPREP + 255) / 256, 256>>>(x, Wq_w, Wk_w, Wv_w);

    {
        dim3 grid(DDIM / 128, BB * NN / 128, 3);
        qkv_mma_kernel<<<grid, 256, SMEM_TOTAL>>>(Wq_b, Wk_b, Wv_b);
    }
    {
        dim3 grid(NN / 128, NN / 128, BB);
        score_mma_kernel<<<grid, 256, SMEM_TOTAL>>>(adj);
    }
    {
        dim3 grid(DDIM / 128, NN / 128, BB);
        out_mma_kernel<<<grid, 256, SMEM_TOTAL>>>(out);
    }
}

// round 10
// speedup vs baseline: 1.1773x; 1.0030x over previous
#include <cuda_runtime.h>
#include <cuda_bf16.h>
#include <cstdint>
#include <cstddef>

#define BB 8
#define NN 2048
#define DDIM 512

typedef __nv_bfloat16 bf16;

// ---------------------------------------------------------------------------
// Scratch (static device globals: allocation-free rule)
// ---------------------------------------------------------------------------
__device__ bf16 g_xh[(size_t)BB * NN * DDIM];
__device__ bf16 g_xl[(size_t)BB * NN * DDIM];
__device__ bf16 g_wqh[(size_t)DDIM * DDIM];
__device__ bf16 g_wql[(size_t)DDIM * DDIM];
__device__ bf16 g_wkh[(size_t)DDIM * DDIM];
__device__ bf16 g_wkl[(size_t)DDIM * DDIM];
__device__ bf16 g_wvh[(size_t)DDIM * DDIM];
__device__ bf16 g_wvl[(size_t)DDIM * DDIM];
__device__ bf16 g_Qh[(size_t)BB * NN * DDIM];
__device__ bf16 g_Ql[(size_t)BB * NN * DDIM];
__device__ bf16 g_Kh[(size_t)BB * NN * DDIM];
__device__ bf16 g_Kl[(size_t)BB * NN * DDIM];
__device__ bf16 g_Vh[(size_t)BB * NN * DDIM];
__device__ bf16 g_Vl[(size_t)BB * NN * DDIM];
__device__ bf16 g_Wmh[(size_t)BB * NN * NN];
__device__ bf16 g_Wml[(size_t)BB * NN * NN];
__device__ float g_rs[(size_t)BB * NN];

// ---------------------------------------------------------------------------
// Low-level helpers (family-baseline PTX only: cp.async / ldmatrix / mma.sync)
// ---------------------------------------------------------------------------
__device__ __forceinline__ uint32_t smem_to_u32(const void* p) {
    uint32_t a;
    asm("{ .reg .u64 t; cvta.to.shared.u64 t, %1; cvt.u32.u64 %0, t; }"
        : "=r"(a) : "l"(p));
    return a;
}
__device__ __forceinline__ void cp16(uint32_t dst, const void* src) {
    asm volatile("cp.async.cg.shared.global [%0], [%1], 16;" :: "r"(dst), "l"(src));
}
__device__ __forceinline__ void cp_commit() {
    asm volatile("cp.async.commit_group;" ::: "memory");
}
__device__ __forceinline__ void cp_wait1() {
    asm volatile("cp.async.wait_group 1;" ::: "memory");
}
__device__ __forceinline__ void cp_wait0() {
    asm volatile("cp.async.wait_group 0;" ::: "memory");
}
__device__ __forceinline__ void ldsm4(uint32_t* r, uint32_t addr) {
    asm volatile("ldmatrix.sync.aligned.m8n8.x4.shared.b16 {%0,%1,%2,%3}, [%4];"
                 : "=r"(r[0]), "=r"(r[1]), "=r"(r[2]), "=r"(r[3]) : "r"(addr));
}
__device__ __forceinline__ void ldsm4t(uint32_t* r, uint32_t addr) {
    asm volatile("ldmatrix.sync.aligned.m8n8.x4.trans.shared.b16 {%0,%1,%2,%3}, [%4];"
                 : "=r"(r[0]), "=r"(r[1]), "=r"(r[2]), "=r"(r[3]) : "r"(addr));
}
__device__ __forceinline__ void mma16816(float* c, const uint32_t* a, const uint32_t* b) {
    asm volatile(
        "mma.sync.aligned.m16n8k16.row.col.f32.bf16.bf16.f32 "
        "{%0,%1,%2,%3}, {%4,%5,%6,%7}, {%8,%9}, {%0,%1,%2,%3};"
        : "+f"(c[0]), "+f"(c[1]), "+f"(c[2]), "+f"(c[3])
        : "r"(a[0]), "r"(a[1]), "r"(a[2]), "r"(a[3]), "r"(b[0]), "r"(b[1]));
}
__device__ __forceinline__ uint32_t pack_bf16(bf16 a, bf16 b) {
    return (uint32_t)__bfloat16_as_ushort(a) | ((uint32_t)__bfloat16_as_ushort(b) << 16);
}
__device__ __forceinline__ void split_val(float v, bf16& h, bf16& l) {
    h = __float2bfloat16(v);
    l = __float2bfloat16(v - __bfloat162float(h));
}

// ---------------------------------------------------------------------------
// SMEM: 3 stages x (Ah 16K | Al 16K | Bh 16K | Bl 16K) = 192 KB
// k-major slab: 128 rows x 128B (64 bf16), XOR-swizzled 16B chunks.
// n-major V slab (out kernel): 64 k-rows x 256B (128 bf16).
// ---------------------------------------------------------------------------
static constexpr int SLAB = 16384;
static constexpr int STAGE = 4 * SLAB;        // 65536
static constexpr int SMEM_TOTAL = 3 * STAGE;  // 196608

// k-major loader: 128 rows x 64 k. 256 threads, 4 cp16 each.
__device__ __forceinline__ void load_km(const bf16* src, size_t ld, uint32_t sbase, int t)
{
    const int col = t & 7, r0 = t >> 3;   // r0: 0..31
    #pragma unroll
    for (int p = 0; p < 4; p++) {
        const int row = r0 + 32 * p;
        const uint32_t off = row * 128 + ((col ^ (row & 7)) << 4);
        cp16(sbase + off, src + (size_t)row * ld + col * 8);
    }
}
// n-major V loader: 64 k-rows x 128 n-cols. 256 threads, 4 cp16 each.
__device__ __forceinline__ void load_bn(const bf16* src, size_t ld, uint32_t sbase, int t)
{
    const int col = t & 15, r0 = t >> 4;  // r0: 0..15
    #pragma unroll
    for (int p = 0; p < 4; p++) {
        const int row = r0 + 16 * p;
        const uint32_t off = row * 256 + ((col ^ (row & 7)) << 4);
        cp16(sbase + off, src + (size_t)row * ld + col * 8);
    }
}

// ---------------------------------------------------------------------------
// Fragment loaders (one kk step = 16 k-values)
// ---------------------------------------------------------------------------
__device__ __forceinline__ void lda_frag(uint32_t sAh, uint32_t sAl, int kk, int lane,
                                         int wm0, uint32_t aH[4][4], uint32_t aL[4][4])
{
    const int ar = lane & 15;
    const int ac = 2 * kk + (lane >> 4);
    #pragma unroll
    for (int i = 0; i < 4; i++) {
        const int row = wm0 + i * 16 + ar;
        const uint32_t off = row * 128 + ((ac ^ (row & 7)) << 4);
        ldsm4(aH[i], sAh + off);
        ldsm4(aL[i], sAl + off);
    }
}
__device__ __forceinline__ void ldb_frag_nt(uint32_t sBh, uint32_t sBl, int kk, int lane,
                                            int wn0, uint32_t bH[4][2], uint32_t bL[4][2])
{
    const int br = (lane & 7) + ((lane >> 4) & 1) * 8;
    const int bc = 2 * kk + ((lane >> 3) & 1);
    #pragma unroll
    for (int jj = 0; jj < 2; jj++) {
        const int row = wn0 + jj * 16 + br;
        const uint32_t off = row * 128 + ((bc ^ (row & 7)) << 4);
        uint32_t tH[4], tL[4];
        ldsm4(tH, sBh + off);
        ldsm4(tL, sBl + off);
        bH[2 * jj][0] = tH[0]; bH[2 * jj][1] = tH[1];
        bH[2 * jj + 1][0] = tH[2]; bH[2 * jj + 1][1] = tH[3];
        bL[2 * jj][0] = tL[0]; bL[2 * jj][1] = tL[1];
        bL[2 * jj + 1][0] = tL[2]; bL[2 * jj + 1][1] = tL[3];
    }
}
__device__ __forceinline__ void ldb_frag_tr(uint32_t sVh, uint32_t sVl, int kk, int lane,
                                            int wn0, uint32_t bH[4][2], uint32_t bL[4][2])
{
    const int br = kk * 16 + (lane & 7) + ((lane >> 3) & 1) * 8;
    #pragma unroll
    for (int jj = 0; jj < 2; jj++) {
        const int ch = (wn0 >> 3) + 2 * jj + (lane >> 4);
        const uint32_t off = br * 256 + ((ch ^ (br & 7)) << 4);
        uint32_t tH[4], tL[4];
        ldsm4t(tH, sVh + off);
        ldsm4t(tL, sVl + off);
        bH[2 * jj][0] = tH[0]; bH[2 * jj][1] = tH[1];
        bH[2 * jj + 1][0] = tH[2]; bH[2 * jj + 1][1] = tH[3];
        bL[2 * jj][0] = tL[0]; bL[2 * jj][1] = tL[1];
        bL[2 * jj + 1][0] = tL[2]; bL[2 * jj + 1][1] = tL[3];
    }
}

// 48 MMAs of one kk step, PASS-MAJOR order: each pass is 16 independent
// accumulators, so same-accumulator RAW reuse distance = 16 instructions
// (asm volatile blocks compiler reordering — the order here IS the SASS order).
__device__ __forceinline__ void mma_block(float c[4][4][4],
                                          uint32_t aH[4][4], uint32_t aL[4][4],
                                          uint32_t bH[4][2], uint32_t bL[4][2])
{
    #pragma unroll
    for (int j = 0; j < 4; j++)
        #pragma unroll
        for (int i = 0; i < 4; i++)
            mma16816(c[i][j], aH[i], bH[j]);
    #pragma unroll
    for (int j = 0; j < 4; j++)
        #pragma unroll
        for (int i = 0; i < 4; i++)
            mma16816(c[i][j], aH[i], bL[j]);
    #pragma unroll
    for (int j = 0; j < 4; j++)
        #pragma unroll
        for (int i = 0; i < 4; i++)
            mma16816(c[i][j], aL[i], bH[j]);
}

// Software-pipelined compute over one 64-k chunk: fragment regs double-buffered;
// kk+1's 12 ldmatrix issue before kk's 48 MMAs so LDS latency hides under HMMA.
__device__ __forceinline__ void compute_nt(uint32_t base, float c[4][4][4],
                                           int lane, int wm0, int wn0)
{
    const uint32_t sAh = base, sAl = base + SLAB;
    const uint32_t sBh = base + 2 * SLAB, sBl = base + 3 * SLAB;
    uint32_t aH[2][4][4], aL[2][4][4], bH[2][4][2], bL[2][4][2];
    lda_frag(sAh, sAl, 0, lane, wm0, aH[0], aL[0]);
    ldb_frag_nt(sBh, sBl, 0, lane, wn0, bH[0], bL[0]);
    #pragma unroll
    for (int kk = 0; kk < 4; kk++) {
        const int cur = kk & 1;
        if (kk < 3) {
            lda_frag(sAh, sAl, kk + 1, lane, wm0, aH[cur ^ 1], aL[cur ^ 1]);
            ldb_frag_nt(sBh, sBl, kk + 1, lane, wn0, bH[cur ^ 1], bL[cur ^ 1]);
        }
        mma_block(c, aH[cur], aL[cur], bH[cur], bL[cur]);
    }
}

__device__ __forceinline__ void compute_tr(uint32_t base, float c[4][4][4],
                                           int lane, int wm0, int wn0)
{
    const uint32_t sAh = base, sAl = base + SLAB;
    const uint32_t sVh = base + 2 * SLAB, sVl = base + 3 * SLAB;
    uint32_t aH[2][4][4], aL[2][4][4], bH[2][4][2], bL[2][4][2];
    lda_frag(sAh, sAl, 0, lane, wm0, aH[0], aL[0]);
    ldb_frag_tr(sVh, sVl, 0, lane, wn0, bH[0], bL[0]);
    #pragma unroll
    for (int kk = 0; kk < 4; kk++) {
        const int cur = kk & 1;
        if (kk < 3) {
            lda_frag(sAh, sAl, kk + 1, lane, wm0, aH[cur ^ 1], aL[cur ^ 1]);
            ldb_frag_tr(sVh, sVl, kk + 1, lane, wn0, bH[cur ^ 1], bL[cur ^ 1]);
        }
        mma_block(c, aH[cur], aL[cur], bH[cur], bL[cur]);
    }
}

#define ZERO_ACC(c)                                  \
    _Pragma("unroll")                                \
    for (int i = 0; i < 4; i++)                      \
        _Pragma("unroll")                            \
        for (int j = 0; j < 4; j++)                  \
            _Pragma("unroll")                        \
            for (int k = 0; k < 4; k++) c[i][j][k] = 0.f;

// ---------------------------------------------------------------------------
// Kernel 1: QKV projections. CTA tile 128(m) x 128(n), 256 threads.
// 3-stage pipeline, one __syncthreads per chunk.
// ---------------------------------------------------------------------------
__global__ __launch_bounds__(256, 1)
void qkv_mma_kernel(const float* __restrict__ bq, const float* __restrict__ bk,
                    const float* __restrict__ bv)
{
    extern __shared__ char smem[];
    const uint32_t sb = smem_to_u32(smem);
    const int tid = threadIdx.x, wid = tid >> 5, lane = tid & 31;
    const int wm0 = (wid & 1) * 64, wn0 = (wid >> 1) * 32;

    const int n0 = blockIdx.x * 128, m0 = blockIdx.y * 128, z = blockIdx.z;
    const bf16 *Wh_, *Wl_;
    const float* bias;
    bf16 *Dh, *Dl;
    if (z == 0)      { Wh_ = g_wqh; Wl_ = g_wql; bias = bq; Dh = g_Qh; Dl = g_Ql; }
    else if (z == 1) { Wh_ = g_wkh; Wl_ = g_wkl; bias = bk; Dh = g_Kh; Dl = g_Kl; }
    else             { Wh_ = g_wvh; Wl_ = g_wvl; bias = bv; Dh = g_Vh; Dl = g_Vl; }

    const bf16* Ah = g_xh + (size_t)m0 * DDIM;
    const bf16* Al = g_xl + (size_t)m0 * DDIM;
    const bf16* Bh = Wh_ + (size_t)n0 * DDIM;
    const bf16* Bl = Wl_ + (size_t)n0 * DDIM;

    const int NIT = DDIM / 64;
    #pragma unroll
    for (int s = 0; s < 2; s++) {
        const uint32_t d = sb + s * STAGE;
        const size_t ko = (size_t)s * 64;
        load_km(Ah + ko, DDIM, d, tid);
        load_km(Al + ko, DDIM, d + SLAB, tid);
        load_km(Bh + ko, DDIM, d + 2 * SLAB, tid);
        load_km(Bl + ko, DDIM, d + 3 * SLAB, tid);
        cp_commit();
    }

    float c[4][4][4];
    ZERO_ACC(c);

    for (int it = 0; it < NIT; it++) {
        if (it < NIT - 1) cp_wait1(); else cp_wait0();
        __syncthreads();
        compute_nt(sb + (it % 3) * STAGE, c, lane, wm0, wn0);
        if (it + 2 < NIT) {
            const uint32_t d = sb + ((it + 2) % 3) * STAGE;
            const size_t ko = (size_t)(it + 2) * 64;
            load_km(Ah + ko, DDIM, d, tid);
            load_km(Al + ko, DDIM, d + SLAB, tid);
            load_km(Bh + ko, DDIM, d + 2 * SLAB, tid);
            load_km(Bl + ko, DDIM, d + 3 * SLAB, tid);
            cp_commit();
        }
    }

    #pragma unroll
    for (int i = 0; i < 4; i++)
        #pragma unroll
        for (int h = 0; h < 2; h++) {
            const int m = m0 + wm0 + i * 16 + (lane >> 2) + 8 * h;
            #pragma unroll
            for (int j = 0; j < 4; j++) {
                const int col = n0 + wn0 + j * 8 + 2 * (lane & 3);
                const float2 bs = *(const float2*)(bias + col);
                const float v0 = c[i][j][2 * h] + bs.x;
                const float v1 = c[i][j][2 * h + 1] + bs.y;
                bf16 h0, h1, l0, l1;
                split_val(v0, h0, l0);
                split_val(v1, h1, l1);
                const size_t idx = (size_t)m * DDIM + col;
                *(uint32_t*)(Dh + idx) = pack_bf16(h0, h1);
                *(uint32_t*)(Dl + idx) = pack_bf16(l0, l1);
            }
        }
}

// ---------------------------------------------------------------------------
// Kernel 2: scores + mask*exp + split store W + fused rowsum atomics.
// CTA tile 128(q) x 128(c), 256 threads, 3-stage/1-sync.
// ---------------------------------------------------------------------------
__global__ __launch_bounds__(256, 1)
void score_mma_kernel(const float* __restrict__ adj)
{
    extern __shared__ char smem[];
    const uint32_t sb = smem_to_u32(smem);
    const int tid = threadIdx.x, wid = tid >> 5, lane = tid & 31;
    const int wm0 = (wid & 1) * 64, wn0 = (wid >> 1) * 32;

    const int c0 = blockIdx.x * 128, q0 = blockIdx.y * 128, b = blockIdx.z;

    const bf16* Ah = g_Qh + ((size_t)b * NN + q0) * DDIM;
    const bf16* Al = g_Ql + ((size_t)b * NN + q0) * DDIM;
    const bf16* Bh = g_Kh + ((size_t)b * NN + c0) * DDIM;
    const bf16* Bl = g_Kl + ((size_t)b * NN + c0) * DDIM;

    const int NIT = DDIM / 64;
    #pragma unroll
    for (int s = 0; s < 2; s++) {
        const uint32_t d = sb + s * STAGE;
        const size_t ko = (size_t)s * 64;
        load_km(Ah + ko, DDIM, d, tid);
        load_km(Al + ko, DDIM, d + SLAB, tid);
        load_km(Bh + ko, DDIM, d + 2 * SLAB, tid);
        load_km(Bl + ko, DDIM, d + 3 * SLAB, tid);
        cp_commit();
    }

    float c[4][4][4];
    ZERO_ACC(c);

    for (int it = 0; it < NIT; it++) {
        if (it < NIT - 1) cp_wait1(); else cp_wait0();
        __syncthreads();
        compute_nt(sb + (it % 3) * STAGE, c, lane, wm0, wn0);
        if (it + 2 < NIT) {
            const uint32_t d = sb + ((it + 2) % 3) * STAGE;
            const size_t ko = (size_t)(it + 2) * 64;
            load_km(Ah + ko, DDIM, d, tid);
            load_km(Al + ko, DDIM, d + SLAB, tid);
            load_km(Bh + ko, DDIM, d + 2 * SLAB, tid);
            load_km(Bl + ko, DDIM, d + 3 * SLAB, tid);
            cp_commit();
        }
    }

    #pragma unroll
    for (int i = 0; i < 4; i++)
        #pragma unroll
        for (int h = 0; h < 2; h++) {
            const int r = q0 + wm0 + i * 16 + (lane >> 2) + 8 * h;
            const size_t rowbase = ((size_t)b * NN + r) * NN;
            float rsum = 0.f;
            #pragma unroll
            for (int j = 0; j < 4; j++) {
                const int cc = c0 + wn0 + j * 8 + 2 * (lane & 3);
                const float2 a2 = *(const float2*)(adj + rowbase + cc);
                const float w0 = a2.x * __expf(c[i][j][2 * h]);
                const float w1 = a2.y * __expf(c[i][j][2 * h + 1]);
                rsum += w0 + w1;
                bf16 h0, h1, l0, l1;
                split_val(w0, h0, l0);
                split_val(w1, h1, l1);
                *(uint32_t*)(g_Wmh + rowbase + cc) = pack_bf16(h0, h1);
                *(uint32_t*)(g_Wml + rowbase + cc) = pack_bf16(l0, l1);
            }
            rsum += __shfl_xor_sync(0xffffffffu, rsum, 1);
            rsum += __shfl_xor_sync(0xffffffffu, rsum, 2);
            if ((lane & 3) == 0)
                atomicAdd(&g_rs[b * NN + r], rsum);
        }
}

// ---------------------------------------------------------------------------
// Kernel 3: O = (W @ V) / rowsum.  CTA tile 128(q) x 128(n), 3-stage/1-sync.
// ---------------------------------------------------------------------------
__global__ __launch_bounds__(256, 1)
void out_mma_kernel(float* __restrict__ out)
{
    extern __shared__ char smem[];
    const uint32_t sb = smem_to_u32(smem);
    const int tid = threadIdx.x, wid = tid >> 5, lane = tid & 31;
    const int wm0 = (wid & 1) * 64, wn0 = (wid >> 1) * 32;

    const int n0 = blockIdx.x * 128, q0 = blockIdx.y * 128, b = blockIdx.z;

    const bf16* Ah = g_Wmh + ((size_t)b * NN + q0) * NN;
    const bf16* Al = g_Wml + ((size_t)b * NN + q0) * NN;
    const bf16* Bh = g_Vh + (size_t)b * NN * DDIM + n0;
    const bf16* Bl = g_Vl + (size_t)b * NN * DDIM + n0;

    const int NIT = NN / 64;
    #pragma unroll
    for (int s = 0; s < 2; s++) {
        const uint32_t d = sb + s * STAGE;
        const size_t ko = (size_t)s * 64;
        load_km(Ah + ko, NN, d, tid);
        load_km(Al + ko, NN, d + SLAB, tid);
        load_bn(Bh + ko * DDIM, DDIM, d + 2 * SLAB, tid);
        load_bn(Bl + ko * DDIM, DDIM, d + 3 * SLAB, tid);
        cp_commit();
    }

    float c[4][4][4];
    ZERO_ACC(c);

    for (int it = 0; it < NIT; it++) {
        if (it < NIT - 1) cp_wait1(); else cp_wait0();
        __syncthreads();
        compute_tr(sb + (it % 3) * STAGE, c, lane, wm0, wn0);
        if (it + 2 < NIT) {
            const uint32_t d = sb + ((it + 2) % 3) * STAGE;
            const size_t ko = (size_t)(it + 2) * 64;
            load_km(Ah + ko, NN, d, tid);
            load_km(Al + ko, NN, d + SLAB, tid);
            load_bn(Bh + ko * DDIM, DDIM, d + 2 * SLAB, tid);
            load_bn(Bl + ko * DDIM, DDIM, d + 3 * SLAB, tid);
            cp_commit();
        }
    }

    #pragma unroll
    for (int i = 0; i < 4; i++)
        #pragma unroll
        for (int h = 0; h < 2; h++) {
            const int r = q0 + wm0 + i * 16 + (lane >> 2) + 8 * h;
            const float inv = 1.0f / g_rs[b * NN + r];
            float* op = out + ((size_t)b * NN + r) * DDIM;
            #pragma unroll
            for (int j = 0; j < 4; j++) {
                const int col = n0 + wn0 + j * 8 + 2 * (lane & 3);
                float2 v;
                v.x = c[i][j][2 * h] * inv;
                v.y = c[i][j][2 * h + 1] * inv;
                *(float2*)(op + col) = v;
            }
        }
}

// ---------------------------------------------------------------------------
// Prep: all fp32 -> (hi, lo) bf16 splits + rowsum zero, ONE launch.
// ---------------------------------------------------------------------------
static constexpr int NX4 = BB * NN * DDIM / 4;
static constexpr int NW4 = DDIM * DDIM / 4;
static constexpr int NPREP = NX4 + 3 * NW4;

__global__ void prep_kernel(const float* __restrict__ x,
                            const float* __restrict__ wq,
                            const float* __restrict__ wk,
                            const float* __restrict__ wv)
{
    const int i = blockIdx.x * blockDim.x + threadIdx.x;
    if (i < BB * NN) g_rs[i] = 0.f;
    if (i >= NPREP) return;

    const float* src;
    bf16 *h, *l;
    int j;
    if (i < NX4)               { src = x;  h = g_xh;  l = g_xl;  j = i; }
    else if (i < NX4 + NW4)    { src = wq; h = g_wqh; l = g_wql; j = i - NX4; }
    else if (i < NX4 + 2*NW4)  { src = wk; h = g_wkh; l = g_wkl; j = i - NX4 - NW4; }
    else                       { src = wv; h = g_wvh; l = g_wvl; j = i - NX4 - 2*NW4; }

    float4 v = ((const float4*)src)[j];
    bf16 h0, h1, h2, h3, l0, l1, l2, l3;
    split_val(v.x, h0, l0); split_val(v.y, h1, l1);
    split_val(v.z, h2, l2); split_val(v.w, h3, l3);
    ((uint2*)h)[j] = make_uint2(pack_bf16(h0, h1), pack_bf16(h2, h3));
    ((uint2*)l)[j] = make_uint2(pack_bf16(l0, l1), pack_bf16(l2, l3));
}

// ---------------------------------------------------------------------------
extern "C" void kernel_launch(void* const* d_in, const int* in_sizes, int n_in,
                              void* d_out, int out_size)
{
    const float* x    = (const float*)d_in[0];
    const float* adj  = (const float*)d_in[1];
    const float* Wq_w = (const float*)d_in[2];
    const float* Wq_b = (const float*)d_in[3];
    const float* Wk_w = (const float*)d_in[4];
    const float* Wk_b = (const float*)d_in[5];
    const float* Wv_w = (const float*)d_in[6];
    const float* Wv_b = (const float*)d_in[7];
    float* out = (float*)d_out;

    cudaFuncSetAttribute(qkv_mma_kernel, cudaFuncAttributeMaxDynamicSharedMemorySize, SMEM_TOTAL);
    cudaFuncSetAttribute(score_mma_kernel, cudaFuncAttributeMaxDynamicSharedMemorySize, SMEM_TOTAL);
    cudaFuncSetAttribute(out_mma_kernel, cudaFuncAttributeMaxDynamicSharedMemorySize, SMEM_TOTAL);

    prep_kernel<<<(NPREP + 255) / 256, 256>>>(x, Wq_w, Wk_w, Wv_w);

    {
        dim3 grid(DDIM / 128, BB * NN / 128, 3);
        qkv_mma_kernel<<<grid, 256, SMEM_TOTAL>>>(Wq_b, Wk_b, Wv_b);
    }
    {
        dim3 grid(NN / 128, NN / 128, BB);
        score_mma_kernel<<<grid, 256, SMEM_TOTAL>>>(adj);
    }
    {
        dim3 grid(DDIM / 128, NN / 128, BB);
        out_mma_kernel<<<grid, 256, SMEM_TOTAL>>>(out);
    }
}